// round 13
// baseline (speedup 1.0000x reference)
#include <cuda_runtime.h>
#include <cuda_bf16.h>

#define BB 512
#define LL 2048
#define CC 64
#define START_S 62
#define STOP_S 63
#define MID 1023

// scratch (no cudaMalloc allowed)
__device__ unsigned g_eTbfF[CC * 32]; // fwd:  [cp][k2] = bf16x2{exp(T[2k2][cp]), exp(T[2k2+1][cp])}
__device__ unsigned g_eTbfB[CC * 32]; // bwd:  [c][k2]  = bf16x2{exp(T[c][2k2]),  exp(T[c][2k2+1])}
__device__ float g_eTstop[CC];        // exp(T[c][STOP])
__device__ float g_trow_start[CC];    // T[START][c]
__device__ float g_part[BB];
__device__ float g_scores[BB];

// bf16x2 packed ops
__device__ __forceinline__ unsigned bffma(unsigned a, unsigned b, unsigned c) {
    unsigned d;
    asm("fma.rn.bf16x2 %0, %1, %2, %3;" : "=r"(d) : "r"(a), "r"(b), "r"(c));
    return d;
}
__device__ __forceinline__ unsigned bfadd(unsigned a, unsigned b) {
    unsigned d;
    asm("add.rn.bf16x2 %0, %1, %2;" : "=r"(d) : "r"(a), "r"(b));
    return d;
}
__device__ __forceinline__ float bfsum(unsigned ab) {
    float lo = __uint_as_float(ab << 16);
    float hi = __uint_as_float(ab & 0xffff0000u);
    return lo + hi;
}
__device__ __forceinline__ unsigned bfpack(float x, float y) {
    unsigned d;
    asm("cvt.rn.bf16x2.f32 %0, %1, %2;" : "=r"(d) : "f"(y), "f"(x));
    return d;
}

// ---------------------------------------------------------------------------
// Precompute both packed exp(T) tables + boundary vectors.
// ---------------------------------------------------------------------------
__global__ void prep_kernel(const float* __restrict__ T) {
    int i = blockIdx.x * blockDim.x + threadIdx.x;
    if (i < CC * 32) {
        int c  = i >> 5;
        int k2 = i & 31;
        __nv_bfloat162 pf = __floats2bfloat162_rn(__expf(T[(2 * k2) * CC + c]),
                                                  __expf(T[(2 * k2 + 1) * CC + c]));
        g_eTbfF[i] = *reinterpret_cast<unsigned*>(&pf);
        __nv_bfloat162 pb = __floats2bfloat162_rn(__expf(T[c * CC + 2 * k2]),
                                                  __expf(T[c * CC + 2 * k2 + 1]));
        g_eTbfB[i] = *reinterpret_cast<unsigned*>(&pb);
    }
    if (i < CC) {
        g_eTstop[i]     = __expf(T[i * CC + STOP_S]);
        g_trow_start[i] = T[START_S * CC + i];
    }
}

// FOUR 64-dots: two batches (vA, vB) x two output states, SHARING eA/eB.
// 128 HFMA2, 16 accumulators of depth 8; the two batches' chains interleave.
__device__ __forceinline__ void dot2x2(const unsigned* __restrict__ vA,
                                       const unsigned* __restrict__ vB,
                                       const unsigned* __restrict__ eA,
                                       const unsigned* __restrict__ eB,
                                       float& dA0, float& dA1,
                                       float& dB0, float& dB1) {
    const uint4* qA = reinterpret_cast<const uint4*>(vA);
    const uint4* qB = reinterpret_cast<const uint4*>(vB);
    unsigned pA0 = 0, pA1 = 0, pA2 = 0, pA3 = 0;   // batch A vs eA
    unsigned rA0 = 0, rA1 = 0, rA2 = 0, rA3 = 0;   // batch A vs eB
    unsigned pB0 = 0, pB1 = 0, pB2 = 0, pB3 = 0;   // batch B vs eA
    unsigned rB0 = 0, rB1 = 0, rB2 = 0, rB3 = 0;   // batch B vs eB
#pragma unroll
    for (int j = 0; j < 8; ++j) {
        uint4 x = qA[j];
        uint4 y = qB[j];
        unsigned e0 = eA[4 * j + 0], g0 = eB[4 * j + 0];
        unsigned e1 = eA[4 * j + 1], g1 = eB[4 * j + 1];
        unsigned e2 = eA[4 * j + 2], g2 = eB[4 * j + 2];
        unsigned e3 = eA[4 * j + 3], g3 = eB[4 * j + 3];
        pA0 = bffma(x.x, e0, pA0);  pB0 = bffma(y.x, e0, pB0);
        rA0 = bffma(x.x, g0, rA0);  rB0 = bffma(y.x, g0, rB0);
        pA1 = bffma(x.y, e1, pA1);  pB1 = bffma(y.y, e1, pB1);
        rA1 = bffma(x.y, g1, rA1);  rB1 = bffma(y.y, g1, rB1);
        pA2 = bffma(x.z, e2, pA2);  pB2 = bffma(y.z, e2, pB2);
        rA2 = bffma(x.z, g2, rA2);  rB2 = bffma(y.z, g2, rB2);
        pA3 = bffma(x.w, e3, pA3);  pB3 = bffma(y.w, e3, pB3);
        rA3 = bffma(x.w, g3, rA3);  rB3 = bffma(y.w, g3, rB3);
    }
    dA0 = bfsum(bfadd(bfadd(pA0, pA1), bfadd(pA2, pA3)));
    dA1 = bfsum(bfadd(bfadd(rA0, rA1), bfadd(rA2, rA3)));
    dB0 = bfsum(bfadd(bfadd(pB0, pB1), bfadd(pB2, pB3)));
    dB1 = bfsum(bfadd(bfadd(rB0, rB1), bfadd(rB2, rB3)));
}

// forward superstep for TWO batches. MODE: 0 plain, 1 launch maxes, 2 renorm.
template <int MODE>
__device__ __forceinline__ void stepF2(float2 eva, float mka, float2 evb, float mkvb,
                                       float& va0, float& va1, float& Sa, float& mxa,
                                       float& vb0, float& vb1, float& Sb_, float& mxb,
                                       int& cur, unsigned (*vA)[32], unsigned (*vB)[32],
                                       const unsigned* __restrict__ eA,
                                       const unsigned* __restrict__ eB, int lane) {
    if (MODE == 1) {
        float x = fmaxf(va0, va1);
        float y = fmaxf(vb0, vb1);
#pragma unroll
        for (int o = 16; o; o >>= 1) {
            x = fmaxf(x, __shfl_xor_sync(0xffffffffu, x, o));
            y = fmaxf(y, __shfl_xor_sync(0xffffffffu, y, o));
        }
        mxa = x; mxb = y;
    }
    float fa0 = __expf(eva.x), fa1 = __expf(eva.y);
    float fb0 = __expf(evb.x), fb1 = __expf(evb.y);
    float vra0 = va0, vra1 = va1, vrb0 = vb0, vrb1 = vb1;
    if (MODE == 2) {
        float rA = __fdividef(1.0f, mxa);
        float rB = __fdividef(1.0f, mxb);
        Sa  += __logf(mxa);
        Sb_ += __logf(mxb);
        fa0 *= rA; fa1 *= rA; vra0 *= rA; vra1 *= rA;
        fb0 *= rB; fb1 *= rB; vrb0 *= rB; vrb1 *= rB;
    }
    float dA0, dA1, dB0, dB1;
    dot2x2(vA[cur], vB[cur], eA, eB, dA0, dA1, dB0, dB1);
    va0 = (mka  > 0.f) ? dA0 * fa0 : vra0;
    va1 = (mka  > 0.f) ? dA1 * fa1 : vra1;
    vb0 = (mkvb > 0.f) ? dB0 * fb0 : vrb0;
    vb1 = (mkvb > 0.f) ? dB1 * fb1 : vrb1;
    vA[cur ^ 1][lane] = bfpack(va0, va1);
    vB[cur ^ 1][lane] = bfpack(vb0, vb1);
    __syncwarp();
    cur ^= 1;
}

// backward superstep for TWO batches (emission applied BEFORE the dot).
template <int MODE>
__device__ __forceinline__ void stepB2(float2 eva, float mka, float2 evb, float mkvb,
                                       float& va0, float& va1, float& Sa, float& mxa,
                                       float& vb0, float& vb1, float& Sb_, float& mxb,
                                       int& cur, unsigned (*vA)[32], unsigned (*vB)[32],
                                       const unsigned* __restrict__ eA,
                                       const unsigned* __restrict__ eB, int lane) {
    if (MODE == 1) {
        float x = fmaxf(va0, va1);
        float y = fmaxf(vb0, vb1);
#pragma unroll
        for (int o = 16; o; o >>= 1) {
            x = fmaxf(x, __shfl_xor_sync(0xffffffffu, x, o));
            y = fmaxf(y, __shfl_xor_sync(0xffffffffu, y, o));
        }
        mxa = x; mxb = y;
    }
    float fa0 = __expf(eva.x), fa1 = __expf(eva.y);
    float fb0 = __expf(evb.x), fb1 = __expf(evb.y);
    float vra0 = va0, vra1 = va1, vrb0 = vb0, vrb1 = vb1;
    if (MODE == 2) {
        float rA = __fdividef(1.0f, mxa);
        float rB = __fdividef(1.0f, mxb);
        Sa  += __logf(mxa);
        Sb_ += __logf(mxb);
        fa0 *= rA; fa1 *= rA; vra0 *= rA; vra1 *= rA;
        fb0 *= rB; fb1 *= rB; vrb0 *= rB; vrb1 *= rB;
    }
    int nxt = cur ^ 1;
    vA[nxt][lane] = bfpack(va0 * fa0, va1 * fa1);   // u = e⊙w (renorm folded)
    vB[nxt][lane] = bfpack(vb0 * fb0, vb1 * fb1);
    __syncwarp();
    float dA0, dA1, dB0, dB1;
    dot2x2(vA[nxt], vB[nxt], eA, eB, dA0, dA1, dB0, dB1);
    va0 = (mka  > 0.f) ? dA0 : vra0;
    va1 = (mka  > 0.f) ? dA1 : vra1;
    vb0 = (mkvb > 0.f) ? dB0 : vrb0;
    vb1 = (mkvb > 0.f) ? dB1 : vrb1;
    cur = nxt;
}

// ---------------------------------------------------------------------------
// Bidirectional forward algorithm, TWO same-direction batches per warp.
// 128 CTAs x 128 threads; warps = fwd(b0,b1), bwd(b0,b1), fwd(b2,b3),
// bwd(b2,b3) -> 512 warps, exactly 1 per SMSP. The two batches SHARE the
// 64-register exp(T) table, and their independent dots interleave in dot2x2
// to hide each other's LDS/FMA latency. One __syncwarp per superstep;
// __syncthreads only once at the end to join fwd/bwd halves:
//   logZ = log( sum_c alpha_MID[c] * w_MID[c] ) + S_f + S_b.
// Renorm every 4 supersteps, max-shuffles pipelined off the chain.
// ---------------------------------------------------------------------------
__global__ void __launch_bounds__(128, 1) alpha_kernel(const float* __restrict__ em,
                                                       const float* __restrict__ mask) {
    const int lane  = threadIdx.x & 31;
    const int wid   = threadIdx.x >> 5;
    const int pairi = wid >> 1;          // batch-pair slot in CTA (0 or 1)
    const int dir   = wid & 1;           // 0 = forward, 1 = backward
    const int bA    = blockIdx.x * 4 + pairi * 2;

    __shared__ __align__(16) unsigned vbuf[4][2][2][32];  // [warp][batch][buf][lane]
    __shared__ float warr[4][CC];                          // [slot][state]
    __shared__ float sSb[4];

    unsigned (*vA)[32] = vbuf[wid][0];
    unsigned (*vB)[32] = vbuf[wid][1];
    const int slotA = pairi * 2, slotB = slotA + 1;

    const float* embA = em + (size_t)bA * (LL * CC);
    const float* embB = embA + (size_t)LL * CC;
    const float* mkbA = mask + (size_t)bA * LL;
    const float* mkbB = mkbA + LL;
    const float2* e2A = reinterpret_cast<const float2*>(embA) + lane;
    const float2* e2B = reinterpret_cast<const float2*>(embB) + lane;

    float va0, va1, Sa = 0.0f, mxa = 0.0f;
    float vb0, vb1, Sb_ = 0.0f, mxb = 0.0f;

    if (dir == 0) {
        // ---------------- forward halves: steps 1..MID ----------------
        unsigned eA[32], eB[32];
        {
            const unsigned* ga = g_eTbfF + (2 * lane) * 32;
            const unsigned* gb = g_eTbfF + (2 * lane + 1) * 32;
#pragma unroll
            for (int k = 0; k < 32; ++k) { eA[k] = ga[k]; eB[k] = gb[k]; }
        }
        float t0s = g_trow_start[2 * lane];
        float t1s = g_trow_start[2 * lane + 1];
        va0 = __expf(e2A[0].x + t0s);
        va1 = __expf(e2A[0].y + t1s);
        vb0 = __expf(e2B[0].x + t0s);
        vb1 = __expf(e2B[0].y + t1s);
        vA[0][lane] = bfpack(va0, va1);
        vB[0][lane] = bfpack(vb0, vb1);

        float2 fa = e2A[1 * 32], fb = e2A[2 * 32], fc = e2A[3 * 32];
        float2 ga = e2B[1 * 32], gb = e2B[2 * 32], gc = e2B[3 * 32];
        float  na = mkbA[1], nb = mkbA[2], nc = mkbA[3];
        float  oa = mkbB[1], ob = mkbB[2], oc = mkbB[3];
        __syncwarp();

        int cur = 0;
#define ADVF(t_)                                                        \
        {                                                               \
            int ti = (t_) + 3; if (ti > MID) ti = MID;                  \
            float2 enA = e2A[(size_t)ti * 32];                          \
            float2 enB = e2B[(size_t)ti * 32];                          \
            float  mnA = mkbA[ti], mnB = mkbB[ti];                      \
            fa = fb; na = nb; fb = fc; nb = nc; fc = enA; nc = mnA;     \
            ga = gb; oa = ob; gb = gc; ob = oc; gc = enB; oc = mnB;     \
        }
#define SF(MODE, t_)                                                    \
        {                                                               \
            float2 xa = fa, xb = ga; float ya = na, yb = oa;            \
            ADVF(t_);                                                   \
            stepF2<MODE>(xa, ya, xb, yb, va0, va1, Sa, mxa,             \
                         vb0, vb1, Sb_, mxb, cur, vA, vB, eA, eB, lane);\
        }
#pragma unroll 1
        for (int t = 1; t <= MID - 3; t += 4) {
            SF(1, t); SF(2, t + 1); SF(0, t + 2); SF(0, t + 3);
        }
#pragma unroll 1
        for (int t = MID - 2; t <= MID; ++t) { SF(0, t); }
#undef SF
#undef ADVF
    } else {
        // ---------------- backward halves: steps L-2 .. MID ----------------
        unsigned eA[32], eB[32];
        {
            const unsigned* ga_ = g_eTbfB + (2 * lane) * 32;
            const unsigned* gb_ = g_eTbfB + (2 * lane + 1) * 32;
#pragma unroll
            for (int k = 0; k < 32; ++k) { eA[k] = ga_[k]; eB[k] = gb_[k]; }
        }
        va0 = g_eTstop[2 * lane];
        va1 = g_eTstop[2 * lane + 1];
        vb0 = va0;
        vb1 = va1;

        float2 fa = e2A[(size_t)(LL - 1) * 32], fb = e2A[(size_t)(LL - 2) * 32],
               fc = e2A[(size_t)(LL - 3) * 32];
        float2 ga = e2B[(size_t)(LL - 1) * 32], gb = e2B[(size_t)(LL - 2) * 32],
               gc = e2B[(size_t)(LL - 3) * 32];
        float  na = mkbA[LL - 1], nb = mkbA[LL - 2], nc = mkbA[LL - 3];
        float  oa = mkbB[LL - 1], ob = mkbB[LL - 2], oc = mkbB[LL - 3];
        __syncwarp();

        int cur = 0;
#define ADVB(t_)                                                        \
        {                                                               \
            int ti = (t_) - 2; if (ti < 0) ti = 0;                      \
            float2 enA = e2A[(size_t)ti * 32];                          \
            float2 enB = e2B[(size_t)ti * 32];                          \
            float  mnA = mkbA[ti], mnB = mkbB[ti];                      \
            fa = fb; na = nb; fb = fc; nb = nc; fc = enA; nc = mnA;     \
            ga = gb; oa = ob; gb = gc; ob = oc; gc = enB; oc = mnB;     \
        }
#define SB(MODE, t_)                                                    \
        {                                                               \
            float2 xa = fa, xb = ga; float ya = na, yb = oa;            \
            ADVB(t_);                                                   \
            stepB2<MODE>(xa, ya, xb, yb, va0, va1, Sa, mxa,             \
                         vb0, vb1, Sb_, mxb, cur, vA, vB, eA, eB, lane);\
        }
        // 256 quads = 1024 steps: emissions LL-1 down to MID+1
#pragma unroll 1
        for (int t = LL - 2; t > MID; t -= 4) {
            SB(1, t); SB(2, t - 1); SB(0, t - 2); SB(0, t - 3);
        }
#undef SB
#undef ADVB
        warr[slotA][2 * lane]     = va0;
        warr[slotA][2 * lane + 1] = va1;
        warr[slotB][2 * lane]     = vb0;
        warr[slotB][2 * lane + 1] = vb1;
        if (lane == 0) { sSb[slotA] = Sa; sSb[slotB] = Sb_; }
    }

    __syncthreads();

    if (dir == 0) {
        // logZ per batch = log( sum_c alpha[c] * w[c] ) + S_f + S_b
        float tA = va0 * warr[slotA][2 * lane] + va1 * warr[slotA][2 * lane + 1];
        float tB = vb0 * warr[slotB][2 * lane] + vb1 * warr[slotB][2 * lane + 1];
#pragma unroll
        for (int o = 16; o; o >>= 1) {
            tA += __shfl_xor_sync(0xffffffffu, tA, o);
            tB += __shfl_xor_sync(0xffffffffu, tB, o);
        }
        if (lane == 0) {
            g_part[bA]     = __logf(tA) + Sa  + sSb[slotA];
            g_part[bA + 1] = __logf(tB) + Sb_ + sSb[slotB];
        }
    }
}

// ---------------------------------------------------------------------------
// Gold path score per batch (cheap gathers) — exact fp32.
// ---------------------------------------------------------------------------
__global__ void __launch_bounds__(256) scores_kernel(const float* __restrict__ em,
                                                     const float* __restrict__ T,
                                                     const float* __restrict__ mask,
                                                     const int* __restrict__ tags) {
    const int b   = blockIdx.x;
    const int tid = threadIdx.x;
    const float* emb = em + (size_t)b * (LL * CC);
    const float* mkb = mask + (size_t)b * LL;
    const int*   tgb = tags + (size_t)b * LL;

    float acc = 0.f, msum = 0.f;
    for (int t = tid; t < LL; t += 256) {
        msum += mkb[t];
        if (t >= 1) {
            int tg = tgb[t];
            int tq = tgb[t - 1];
            acc += (emb[(size_t)t * CC + tg] + T[tq * CC + tg]) * mkb[t];
        }
    }

    __shared__ float sacc[8], smsum[8];
#pragma unroll
    for (int o = 16; o; o >>= 1) {
        acc  += __shfl_xor_sync(0xffffffffu, acc, o);
        msum += __shfl_xor_sync(0xffffffffu, msum, o);
    }
    int lane = tid & 31, w = tid >> 5;
    if (lane == 0) { sacc[w] = acc; smsum[w] = msum; }
    __syncthreads();
    if (tid == 0) {
        float A = 0.f, M = 0.f;
#pragma unroll
        for (int i = 0; i < 8; ++i) { A += sacc[i]; M += smsum[i]; }
        int t0 = tgb[0];
        float s = A + emb[t0] + T[START_S * CC + t0];
        int last = (int)M - 1;               // mask sum of 1.0s is exact in fp32
        s += T[tgb[last] * CC + STOP_S];
        g_scores[b] = s;
    }
}

// ---------------------------------------------------------------------------
// mean(partition - scores)
// ---------------------------------------------------------------------------
__global__ void __launch_bounds__(512) finalize_kernel(float* __restrict__ out) {
    int tid = threadIdx.x;
    float d = g_part[tid] - g_scores[tid];
    __shared__ float sh[16];
#pragma unroll
    for (int o = 16; o; o >>= 1) d += __shfl_xor_sync(0xffffffffu, d, o);
    if ((tid & 31) == 0) sh[tid >> 5] = d;
    __syncthreads();
    if (tid < 16) {
        float x = sh[tid];
#pragma unroll
        for (int o = 8; o; o >>= 1) x += __shfl_xor_sync(0x0000ffffu, x, o);
        if (tid == 0) out[0] = x * (1.0f / BB);
    }
}

extern "C" void kernel_launch(void* const* d_in, const int* in_sizes, int n_in,
                              void* d_out, int out_size) {
    (void)in_sizes; (void)n_in; (void)out_size;
    const float* em   = (const float*)d_in[0];
    const float* T    = (const float*)d_in[1];
    const float* mask = (const float*)d_in[2];
    const int*   tags = (const int*)d_in[3];
    float* out = (float*)d_out;

    prep_kernel<<<4, 512>>>(T);
    alpha_kernel<<<BB / 4, 128>>>(em, mask);
    scores_kernel<<<BB, 256>>>(em, T, mask, tags);
    finalize_kernel<<<1, 512>>>(out);
}

// round 14
// speedup vs baseline: 1.2761x; 1.2761x over previous
#include <cuda_runtime.h>
#include <cuda_bf16.h>

#define BB 512
#define LL 2048
#define CC 64
#define START_S 62
#define STOP_S 63
#define MID 1023

// scratch (no cudaMalloc allowed)
__device__ unsigned g_eTbfF[CC * 32]; // fwd:  [cp][k2] = bf16x2{exp(T[2k2][cp]), exp(T[2k2+1][cp])}
__device__ unsigned g_eTbfB[CC * 32]; // bwd:  [c][k2]  = bf16x2{exp(T[c][2k2]),  exp(T[c][2k2+1])}
__device__ float g_eTstop[CC];        // exp(T[c][STOP])
__device__ float g_trow_start[CC];    // T[START][c]
__device__ float g_part[BB];
__device__ float g_scores[BB];

// bf16x2 packed ops
__device__ __forceinline__ unsigned bffma(unsigned a, unsigned b, unsigned c) {
    unsigned d;
    asm("fma.rn.bf16x2 %0, %1, %2, %3;" : "=r"(d) : "r"(a), "r"(b), "r"(c));
    return d;
}
__device__ __forceinline__ unsigned bfadd(unsigned a, unsigned b) {
    unsigned d;
    asm("add.rn.bf16x2 %0, %1, %2;" : "=r"(d) : "r"(a), "r"(b));
    return d;
}
__device__ __forceinline__ float bfsum(unsigned ab) {
    float lo = __uint_as_float(ab << 16);
    float hi = __uint_as_float(ab & 0xffff0000u);
    return lo + hi;
}
__device__ __forceinline__ unsigned bfpack(float x, float y) {
    unsigned d;
    asm("cvt.rn.bf16x2.f32 %0, %1, %2;" : "=r"(d) : "f"(y), "f"(x));
    return d;
}

// ---------------------------------------------------------------------------
// Precompute both packed exp(T) tables + boundary vectors.
// ---------------------------------------------------------------------------
__global__ void prep_kernel(const float* __restrict__ T) {
    int i = blockIdx.x * blockDim.x + threadIdx.x;
    if (i < CC * 32) {
        int c  = i >> 5;
        int k2 = i & 31;
        __nv_bfloat162 pf = __floats2bfloat162_rn(__expf(T[(2 * k2) * CC + c]),
                                                  __expf(T[(2 * k2 + 1) * CC + c]));
        g_eTbfF[i] = *reinterpret_cast<unsigned*>(&pf);
        __nv_bfloat162 pb = __floats2bfloat162_rn(__expf(T[c * CC + 2 * k2]),
                                                  __expf(T[c * CC + 2 * k2 + 1]));
        g_eTbfB[i] = *reinterpret_cast<unsigned*>(&pb);
    }
    if (i < CC) {
        g_eTstop[i]     = __expf(T[i * CC + STOP_S]);
        g_trow_start[i] = T[START_S * CC + i];
    }
}

// 64-dot for this lane's two output states, input v delivered entirely by
// butterfly shuffles of ONE packed bf16x2 register (no shared memory).
// eA/eB are pre-permuted so eX[j] pairs with shfl.xor(vpack, j).
// 31 SHFL (j=0 uses own vpack) + 64 HFMA2, 8 accumulators of depth 8.
__device__ __forceinline__ void dotsh(unsigned vpack,
                                      const unsigned* __restrict__ eA,
                                      const unsigned* __restrict__ eB,
                                      float& ra, float& rb) {
    unsigned a0, a1 = 0, a2 = 0, a3 = 0;
    unsigned b0, b1 = 0, b2 = 0, b3 = 0;
    a0 = bffma(vpack, eA[0], 0u);          // j = 0: own value
    b0 = bffma(vpack, eB[0], 0u);
#pragma unroll
    for (int j = 1; j < 32; ++j) {
        unsigned u = __shfl_xor_sync(0xffffffffu, vpack, j);
        switch (j & 3) {
            case 0: a0 = bffma(u, eA[j], a0); b0 = bffma(u, eB[j], b0); break;
            case 1: a1 = bffma(u, eA[j], a1); b1 = bffma(u, eB[j], b1); break;
            case 2: a2 = bffma(u, eA[j], a2); b2 = bffma(u, eB[j], b2); break;
            default: a3 = bffma(u, eA[j], a3); b3 = bffma(u, eB[j], b3); break;
        }
    }
    ra = bfsum(bfadd(bfadd(a0, a1), bfadd(a2, a3)));
    rb = bfsum(bfadd(bfadd(b0, b1), bfadd(b2, b3)));
}

// forward step. MODE: 0 plain, 1 launch warp-max of v, 2 apply renorm.
template <int MODE>
__device__ __forceinline__ void stepF(float2 ev, float mkv,
                                      float& v0, float& v1, unsigned& vpack,
                                      float& S, float& mx,
                                      const unsigned* __restrict__ eA,
                                      const unsigned* __restrict__ eB) {
    if (MODE == 1) {            // warp-max of current v — overlaps the dot
        float x = fmaxf(v0, v1);
#pragma unroll
        for (int o = 16; o; o >>= 1) x = fmaxf(x, __shfl_xor_sync(0xffffffffu, x, o));
        mx = x;
    }
    float ee0 = __expf(ev.x);
    float ee1 = __expf(ev.y);
    float vr0 = v0, vr1 = v1;
    if (MODE == 2) {            // fold r = 1/max into emission factor
        float r = __fdividef(1.0f, mx);
        S += __logf(mx);
        ee0 *= r; vr0 = v0 * r;
        ee1 *= r; vr1 = v1 * r;
    }
    float a, bq;
    dotsh(vpack, eA, eB, a, bq);
    v0 = (mkv > 0.f) ? a  * ee0 : vr0;
    v1 = (mkv > 0.f) ? bq * ee1 : vr1;
    vpack = bfpack(v0, v1);
}

// backward step: w' = expT (e ⊙ w) ; emission applied BEFORE the dot.
template <int MODE>
__device__ __forceinline__ void stepB(float2 ev, float mkv,
                                      float& v0, float& v1, float& S, float& mx,
                                      const unsigned* __restrict__ eA,
                                      const unsigned* __restrict__ eB) {
    if (MODE == 1) {
        float x = fmaxf(v0, v1);
#pragma unroll
        for (int o = 16; o; o >>= 1) x = fmaxf(x, __shfl_xor_sync(0xffffffffu, x, o));
        mx = x;
    }
    float ee0 = __expf(ev.x);
    float ee1 = __expf(ev.y);
    float vr0 = v0, vr1 = v1;
    if (MODE == 2) {
        float r = __fdividef(1.0f, mx);
        S += __logf(mx);
        ee0 *= r; vr0 = v0 * r;
        ee1 *= r; vr1 = v1 * r;
    }
    unsigned upack = bfpack(v0 * ee0, v1 * ee1);   // u = e⊙w (renorm folded)
    float a, bq;
    dotsh(upack, eA, eB, a, bq);
    v0 = (mkv > 0.f) ? a  : vr0;
    v1 = (mkv > 0.f) ? bq : vr1;
}

// ---------------------------------------------------------------------------
// Bidirectional forward algorithm in exp-space, bf16 matvec with the state
// vector exchanged ONLY through butterfly shuffles — no shared memory, no
// __syncwarp in the recurrence. 256 CTAs x 128 threads = 2 batches/CTA,
// warps (fwd_b0, bwd_b0, fwd_b1, bwd_b1) covering all 4 SMSPs.
// Lane owns states (2*lane, 2*lane+1); the exp(T) tables are loaded
// pre-permuted by lane^j so dot indexing stays static. fwd runs steps 1..MID,
// bwd runs the transposed recursion from L-1 down to MID+1;
//   logZ = log( sum_c alpha_MID[c] * w_MID[c] ) + S_f + S_b.
// Renorm every 4 steps, max-shuffle pipelined off the chain.
// ---------------------------------------------------------------------------
__global__ void __launch_bounds__(128, 1) alpha_kernel(const float* __restrict__ em,
                                                       const float* __restrict__ mask) {
    const int lane = threadIdx.x & 31;
    const int wid  = threadIdx.x >> 5;
    const int pair = wid >> 1;           // batch slot in CTA (0 or 1)
    const int dir  = wid & 1;            // 0 = forward, 1 = backward
    const int b    = blockIdx.x * 2 + pair;

    __shared__ float warr[2][CC];
    __shared__ float sSb[2];

    const float* emb = em + (size_t)b * (LL * CC);
    const float* mkb = mask + (size_t)b * LL;
    const float2* emb2 = reinterpret_cast<const float2*>(emb) + lane;

    float v0, v1, S = 0.0f, mx = 0.0f;

    if (dir == 0) {
        // ---------------- forward half: steps 1..MID ----------------
        unsigned eA[32], eB[32];
        {
            const unsigned* ga = g_eTbfF + (2 * lane) * 32;
            const unsigned* gb = g_eTbfF + (2 * lane + 1) * 32;
#pragma unroll
            for (int j = 0; j < 32; ++j) {
                int p = lane ^ j;            // input pair delivered at bfly step j
                eA[j] = ga[p];
                eB[j] = gb[p];
            }
        }
        v0 = __expf(emb2[0].x + g_trow_start[2 * lane]);
        v1 = __expf(emb2[0].y + g_trow_start[2 * lane + 1]);
        unsigned vpack = bfpack(v0, v1);

        float2 ea = emb2[1 * 32], eb = emb2[2 * 32], ec = emb2[3 * 32];
        float  ma = mkb[1],       mb = mkb[2],       mc = mkb[3];

#define ADVF(t_)                                                        \
        {                                                               \
            int ti = (t_) + 3; if (ti > MID) ti = MID;                  \
            float2 en = emb2[(size_t)ti * 32];                          \
            float  mn = mkb[ti];                                        \
            ea = eb; ma = mb; eb = ec; mb = mc; ec = en; mc = mn;       \
        }
#define SF(MODE, t_)                                                    \
        {                                                               \
            float2 e0 = ea; float m0 = ma;                              \
            ADVF(t_);                                                   \
            stepF<MODE>(e0, m0, v0, v1, vpack, S, mx, eA, eB);          \
        }
#pragma unroll 1
        for (int t = 1; t <= MID - 3; t += 4) {
            SF(1, t); SF(2, t + 1); SF(0, t + 2); SF(0, t + 3);
        }
#pragma unroll 1
        for (int t = MID - 2; t <= MID; ++t) { SF(0, t); }
#undef SF
#undef ADVF
    } else {
        // ---------------- backward half: steps L-2 .. MID ----------------
        unsigned eA[32], eB[32];
        {
            const unsigned* ga = g_eTbfB + (2 * lane) * 32;
            const unsigned* gb = g_eTbfB + (2 * lane + 1) * 32;
#pragma unroll
            for (int j = 0; j < 32; ++j) {
                int p = lane ^ j;
                eA[j] = ga[p];
                eB[j] = gb[p];
            }
        }
        v0 = g_eTstop[2 * lane];
        v1 = g_eTstop[2 * lane + 1];

        float2 ea = emb2[(size_t)(LL - 1) * 32];
        float2 eb = emb2[(size_t)(LL - 2) * 32];
        float2 ec = emb2[(size_t)(LL - 3) * 32];
        float  ma = mkb[LL - 1], mb = mkb[LL - 2], mc = mkb[LL - 3];

#define ADVB(t_)                                                        \
        {                                                               \
            int ti = (t_) - 2; if (ti < 0) ti = 0;                      \
            float2 en = emb2[(size_t)ti * 32];                          \
            float  mn = mkb[ti];                                        \
            ea = eb; ma = mb; eb = ec; mb = mc; ec = en; mc = mn;       \
        }
#define SB(MODE, t_)                                                    \
        {                                                               \
            float2 e0 = ea; float m0 = ma;                              \
            ADVB(t_);                                                   \
            stepB<MODE>(e0, m0, v0, v1, S, mx, eA, eB);                 \
        }
        // 256 quads = 1024 steps: emissions LL-1 down to MID+1
#pragma unroll 1
        for (int t = LL - 2; t > MID; t -= 4) {
            SB(1, t); SB(2, t - 1); SB(0, t - 2); SB(0, t - 3);
        }
#undef SB
#undef ADVB
        warr[pair][2 * lane]     = v0;
        warr[pair][2 * lane + 1] = v1;
        if (lane == 0) sSb[pair] = S;
    }

    __syncthreads();

    if (dir == 0) {
        // logZ = log( sum_c alpha_MID[c] * w_MID[c] ) + S_f + S_b
        float term = v0 * warr[pair][2 * lane] + v1 * warr[pair][2 * lane + 1];
#pragma unroll
        for (int o = 16; o; o >>= 1) term += __shfl_xor_sync(0xffffffffu, term, o);
        if (lane == 0) g_part[b] = __logf(term) + S + sSb[pair];
    }
}

// ---------------------------------------------------------------------------
// Gold path score per batch (cheap gathers) — exact fp32.
// ---------------------------------------------------------------------------
__global__ void __launch_bounds__(256) scores_kernel(const float* __restrict__ em,
                                                     const float* __restrict__ T,
                                                     const float* __restrict__ mask,
                                                     const int* __restrict__ tags) {
    const int b   = blockIdx.x;
    const int tid = threadIdx.x;
    const float* emb = em + (size_t)b * (LL * CC);
    const float* mkb = mask + (size_t)b * LL;
    const int*   tgb = tags + (size_t)b * LL;

    float acc = 0.f, msum = 0.f;
    for (int t = tid; t < LL; t += 256) {
        msum += mkb[t];
        if (t >= 1) {
            int tg = tgb[t];
            int tq = tgb[t - 1];
            acc += (emb[(size_t)t * CC + tg] + T[tq * CC + tg]) * mkb[t];
        }
    }

    __shared__ float sacc[8], smsum[8];
#pragma unroll
    for (int o = 16; o; o >>= 1) {
        acc  += __shfl_xor_sync(0xffffffffu, acc, o);
        msum += __shfl_xor_sync(0xffffffffu, msum, o);
    }
    int lane = tid & 31, w = tid >> 5;
    if (lane == 0) { sacc[w] = acc; smsum[w] = msum; }
    __syncthreads();
    if (tid == 0) {
        float A = 0.f, M = 0.f;
#pragma unroll
        for (int i = 0; i < 8; ++i) { A += sacc[i]; M += smsum[i]; }
        int t0 = tgb[0];
        float s = A + emb[t0] + T[START_S * CC + t0];
        int last = (int)M - 1;               // mask sum of 1.0s is exact in fp32
        s += T[tgb[last] * CC + STOP_S];
        g_scores[b] = s;
    }
}

// ---------------------------------------------------------------------------
// mean(partition - scores)
// ---------------------------------------------------------------------------
__global__ void __launch_bounds__(512) finalize_kernel(float* __restrict__ out) {
    int tid = threadIdx.x;
    float d = g_part[tid] - g_scores[tid];
    __shared__ float sh[16];
#pragma unroll
    for (int o = 16; o; o >>= 1) d += __shfl_xor_sync(0xffffffffu, d, o);
    if ((tid & 31) == 0) sh[tid >> 5] = d;
    __syncthreads();
    if (tid < 16) {
        float x = sh[tid];
#pragma unroll
        for (int o = 8; o; o >>= 1) x += __shfl_xor_sync(0x0000ffffu, x, o);
        if (tid == 0) out[0] = x * (1.0f / BB);
    }
}

extern "C" void kernel_launch(void* const* d_in, const int* in_sizes, int n_in,
                              void* d_out, int out_size) {
    (void)in_sizes; (void)n_in; (void)out_size;
    const float* em   = (const float*)d_in[0];
    const float* T    = (const float*)d_in[1];
    const float* mask = (const float*)d_in[2];
    const int*   tags = (const int*)d_in[3];
    float* out = (float*)d_out;

    prep_kernel<<<4, 512>>>(T);
    alpha_kernel<<<BB / 2, 128>>>(em, mask);
    scores_kernel<<<BB, 256>>>(em, T, mask, tags);
    finalize_kernel<<<1, 512>>>(out);
}

// round 15
// speedup vs baseline: 1.3796x; 1.0811x over previous
#include <cuda_runtime.h>
#include <cuda_bf16.h>

#define BB 512
#define LL 2048
#define CC 64
#define START_S 62
#define STOP_S 63
#define MID 1023

// scratch (no cudaMalloc allowed)
// packed-per-output tables: entry [k*32 + lane] = bf16x2{ M[k][2lane], M[k][2lane+1] }
__device__ unsigned g_eTpF[CC * 32]; // fwd:  M = exp(T)^T  i.e. {exp(T[2lane? no: see prep])}
__device__ unsigned g_eTpB[CC * 32]; // bwd
__device__ float g_eTstop[CC];       // exp(T[c][STOP])
__device__ float g_trow_start[CC];   // T[START][c]
__device__ float g_part[BB];
__device__ float g_scores[BB];

// bf16x2 packed ops
__device__ __forceinline__ unsigned bffma(unsigned a, unsigned b, unsigned c) {
    unsigned d;
    asm("fma.rn.bf16x2 %0, %1, %2, %3;" : "=r"(d) : "r"(a), "r"(b), "r"(c));
    return d;
}
__device__ __forceinline__ unsigned bfadd(unsigned a, unsigned b) {
    unsigned d;
    asm("add.rn.bf16x2 %0, %1, %2;" : "=r"(d) : "r"(a), "r"(b));
    return d;
}
__device__ __forceinline__ unsigned bfmul(unsigned a, unsigned b) {
    unsigned d;
    asm("mul.rn.bf16x2 %0, %1, %2;" : "=r"(d) : "r"(a), "r"(b));
    return d;
}
__device__ __forceinline__ unsigned bfpack(float x, float y) {
    unsigned d;
    asm("cvt.rn.bf16x2.f32 %0, %1, %2;" : "=r"(d) : "f"(y), "f"(x));
    return d;
}
__device__ __forceinline__ float bflo(unsigned p) { return __uint_as_float(p << 16); }
__device__ __forceinline__ float bfhi(unsigned p) { return __uint_as_float(p & 0xffff0000u); }

// ---------------------------------------------------------------------------
// Precompute packed-per-output exp(T) tables + boundary vectors.
// fwd recursion: v'_{s} = e_s * sum_k v_k * exp(T[k][s])  -> entry[k][lane] =
//   { exp(T[k][2lane]), exp(T[k][2lane+1]) }
// bwd recursion: w'_{s} = sum_k exp(T[s][k]) * u_k        -> entry[k][lane] =
//   { exp(T[2lane][k]), exp(T[2lane+1][k]) }
// ---------------------------------------------------------------------------
__global__ void prep_kernel(const float* __restrict__ T) {
    int i = blockIdx.x * blockDim.x + threadIdx.x;
    if (i < CC * 32) {
        int k    = i >> 5;
        int lane = i & 31;
        __nv_bfloat162 pf = __floats2bfloat162_rn(__expf(T[k * CC + 2 * lane]),
                                                  __expf(T[k * CC + 2 * lane + 1]));
        g_eTpF[i] = *reinterpret_cast<unsigned*>(&pf);
        __nv_bfloat162 pb = __floats2bfloat162_rn(__expf(T[(2 * lane) * CC + k]),
                                                  __expf(T[(2 * lane + 1) * CC + k]));
        g_eTpB[i] = *reinterpret_cast<unsigned*>(&pb);
    }
    if (i < CC) {
        g_eTstop[i]     = __expf(T[i * CC + STOP_S]);
        g_trow_start[i] = T[START_S * CC + i];
    }
}

// packed-output 64-dot: vsh holds 64 duplicated pairs {v_k, v_k}; eT[k] is
// the packed column pair for this lane's two output states. The accumulator
// IS the packed result {d0, d1} — no horizontal sum, no fp32 round-trip.
// 64 HFMA2 into 8 accumulators (depth 8) + 7-op bfadd tree.
__device__ __forceinline__ unsigned dotp(const unsigned* __restrict__ vsh64,
                                         const unsigned* __restrict__ eT) {
    const uint4* q = reinterpret_cast<const uint4*>(vsh64);
    unsigned a0 = 0, a1 = 0, a2 = 0, a3 = 0, a4 = 0, a5 = 0, a6 = 0, a7 = 0;
#pragma unroll
    for (int j = 0; j < 16; j += 2) {
        uint4 x = q[j];
        uint4 y = q[j + 1];
        a0 = bffma(x.x, eT[4 * j + 0], a0);
        a1 = bffma(x.y, eT[4 * j + 1], a1);
        a2 = bffma(x.z, eT[4 * j + 2], a2);
        a3 = bffma(x.w, eT[4 * j + 3], a3);
        a4 = bffma(y.x, eT[4 * j + 4], a4);
        a5 = bffma(y.y, eT[4 * j + 5], a5);
        a6 = bffma(y.z, eT[4 * j + 6], a6);
        a7 = bffma(y.w, eT[4 * j + 7], a7);
    }
    return bfadd(bfadd(bfadd(a0, a1), bfadd(a2, a3)),
                 bfadd(bfadd(a4, a5), bfadd(a6, a7)));
}

// duplicate-pair store: vpack {v0,v1} -> entries 2lane {v0,v0}, 2lane+1 {v1,v1}
__device__ __forceinline__ void dupstore(unsigned* __restrict__ dst, int lane,
                                         unsigned vpack) {
    unsigned dlo = __byte_perm(vpack, 0u, 0x1010);
    unsigned dhi = __byte_perm(vpack, 0u, 0x3232);
    *reinterpret_cast<uint2*>(dst + 2 * lane) = make_uint2(dlo, dhi);
}

// forward step. MODE: 0 plain, 1 launch warp-max of v, 2 apply renorm.
// Entire recurrence in packed bf16x2; fp32 only for off-chain bookkeeping.
template <int MODE>
__device__ __forceinline__ void stepF(float2 ev, float mkv,
                                      unsigned& vpack, float& S, float& mx,
                                      int& cur, unsigned (*vsh)[CC],
                                      const unsigned* __restrict__ eT, int lane) {
    if (MODE == 1) {            // warp-max of current v — overlaps the dot
        float x = fmaxf(bflo(vpack), bfhi(vpack));
#pragma unroll
        for (int o = 16; o; o >>= 1) x = fmaxf(x, __shfl_xor_sync(0xffffffffu, x, o));
        mx = x;
    }
    float ee0 = __expf(ev.x);
    float ee1 = __expf(ev.y);
    unsigned vr = vpack;
    if (MODE == 2) {            // fold r = 1/max into emission factor
        float r = __fdividef(1.0f, mx);
        S += __logf(mx);
        ee0 *= r; ee1 *= r;
        unsigned rp = bfpack(r, r);
        vr = bfmul(vpack, rp);
    }
    unsigned eep = bfpack(ee0, ee1);            // off-chain cvt
    unsigned d   = dotp(vsh[cur], eT);
    unsigned nv  = bfmul(d, eep);
    vpack = (mkv > 0.f) ? nv : vr;
    dupstore(vsh[cur ^ 1], lane, vpack);
    __syncwarp();
    cur ^= 1;
}

// backward step: w' = expT (e ⊙ w) ; emission applied BEFORE the dot.
template <int MODE>
__device__ __forceinline__ void stepB(float2 ev, float mkv,
                                      unsigned& vpack, float& S, float& mx,
                                      int& cur, unsigned (*vsh)[CC],
                                      const unsigned* __restrict__ eT, int lane) {
    if (MODE == 1) {
        float x = fmaxf(bflo(vpack), bfhi(vpack));
#pragma unroll
        for (int o = 16; o; o >>= 1) x = fmaxf(x, __shfl_xor_sync(0xffffffffu, x, o));
        mx = x;
    }
    float ee0 = __expf(ev.x);
    float ee1 = __expf(ev.y);
    unsigned vr = vpack;
    if (MODE == 2) {
        float r = __fdividef(1.0f, mx);
        S += __logf(mx);
        ee0 *= r; ee1 *= r;
        unsigned rp = bfpack(r, r);
        vr = bfmul(vpack, rp);
    }
    unsigned eep = bfpack(ee0, ee1);
    int nxt = cur ^ 1;
    unsigned u = bfmul(vpack, eep);             // u = e⊙w (renorm folded)
    dupstore(vsh[nxt], lane, u);
    __syncwarp();
    unsigned d = dotp(vsh[nxt], eT);
    vpack = (mkv > 0.f) ? d : vr;
    cur = nxt;
}

// ---------------------------------------------------------------------------
// Bidirectional forward algorithm in exp-space, fully-packed bf16 recurrence.
// 256 CTAs x 128 threads = 2 batches/CTA, warps (fwd_b0, bwd_b0, fwd_b1,
// bwd_b1) covering all 4 SMSPs. Lane owns states (2*lane, 2*lane+1); the
// packed-per-output exp(T) column pairs live in 64 registers; v is exchanged
// as 64 duplicated bf16x2 pairs in shared (1 STS.64 + 16 broadcast LDS.128),
// __syncwarp only. The dot's packed accumulator IS {d0,d1} — no horizontal
// sum or fp32/bf16 conversions inside the recurrence. fwd: steps 1..MID;
// bwd: transposed recursion from L-1 down to MID+1;
//   logZ = log( sum_c alpha_MID[c] * w_MID[c] ) + S_f + S_b.
// Renorm every 4 steps, max-shuffle pipelined off the chain.
// ---------------------------------------------------------------------------
__global__ void __launch_bounds__(128, 1) alpha_kernel(const float* __restrict__ em,
                                                       const float* __restrict__ mask) {
    const int lane = threadIdx.x & 31;
    const int wid  = threadIdx.x >> 5;
    const int pair = wid >> 1;           // batch slot in CTA (0 or 1)
    const int dir  = wid & 1;            // 0 = forward, 1 = backward
    const int b    = blockIdx.x * 2 + pair;

    __shared__ __align__(16) unsigned vshbuf[4][2][CC];  // [warp][buf][dup pairs]
    __shared__ float warr[2][CC];
    __shared__ float sSb[2];

    const float* emb = em + (size_t)b * (LL * CC);
    const float* mkb = mask + (size_t)b * LL;
    const float2* emb2 = reinterpret_cast<const float2*>(emb) + lane;

    unsigned (*vsh)[CC] = vshbuf[wid];

    unsigned vpack;
    float S = 0.0f, mx = 0.0f;

    if (dir == 0) {
        // ---------------- forward half: steps 1..MID ----------------
        unsigned eT[CC];
        {
            const unsigned* g = g_eTpF;
#pragma unroll
            for (int k = 0; k < CC; ++k) eT[k] = g[k * 32 + lane];  // coalesced
        }
        float v0 = __expf(emb2[0].x + g_trow_start[2 * lane]);
        float v1 = __expf(emb2[0].y + g_trow_start[2 * lane + 1]);
        vpack = bfpack(v0, v1);
        dupstore(vsh[0], lane, vpack);

        float2 ea = emb2[1 * 32], eb = emb2[2 * 32], ec = emb2[3 * 32];
        float  ma = mkb[1],       mb = mkb[2],       mc = mkb[3];
        __syncwarp();

        int cur = 0;
#define ADVF(t_)                                                        \
        {                                                               \
            int ti = (t_) + 3; if (ti > MID) ti = MID;                  \
            float2 en = emb2[(size_t)ti * 32];                          \
            float  mn = mkb[ti];                                        \
            ea = eb; ma = mb; eb = ec; mb = mc; ec = en; mc = mn;       \
        }
#define SF(MODE, t_)                                                    \
        {                                                               \
            float2 e0 = ea; float m0 = ma;                              \
            ADVF(t_);                                                   \
            stepF<MODE>(e0, m0, vpack, S, mx, cur, vsh, eT, lane);      \
        }
#pragma unroll 1
        for (int t = 1; t <= MID - 3; t += 4) {
            SF(1, t); SF(2, t + 1); SF(0, t + 2); SF(0, t + 3);
        }
#pragma unroll 1
        for (int t = MID - 2; t <= MID; ++t) { SF(0, t); }
#undef SF
#undef ADVF
    } else {
        // ---------------- backward half: steps L-2 .. MID ----------------
        unsigned eT[CC];
        {
            const unsigned* g = g_eTpB;
#pragma unroll
            for (int k = 0; k < CC; ++k) eT[k] = g[k * 32 + lane];
        }
        vpack = bfpack(g_eTstop[2 * lane], g_eTstop[2 * lane + 1]);

        float2 ea = emb2[(size_t)(LL - 1) * 32];
        float2 eb = emb2[(size_t)(LL - 2) * 32];
        float2 ec = emb2[(size_t)(LL - 3) * 32];
        float  ma = mkb[LL - 1], mb = mkb[LL - 2], mc = mkb[LL - 3];
        __syncwarp();

        int cur = 0;
#define ADVB(t_)                                                        \
        {                                                               \
            int ti = (t_) - 2; if (ti < 0) ti = 0;                      \
            float2 en = emb2[(size_t)ti * 32];                          \
            float  mn = mkb[ti];                                        \
            ea = eb; ma = mb; eb = ec; mb = mc; ec = en; mc = mn;       \
        }
#define SB(MODE, t_)                                                    \
        {                                                               \
            float2 e0 = ea; float m0 = ma;                              \
            ADVB(t_);                                                   \
            stepB<MODE>(e0, m0, vpack, S, mx, cur, vsh, eT, lane);      \
        }
        // 256 quads = 1024 steps: emissions LL-1 down to MID+1
#pragma unroll 1
        for (int t = LL - 2; t > MID; t -= 4) {
            SB(1, t); SB(2, t - 1); SB(0, t - 2); SB(0, t - 3);
        }
#undef SB
#undef ADVB
        warr[pair][2 * lane]     = bflo(vpack);
        warr[pair][2 * lane + 1] = bfhi(vpack);
        if (lane == 0) sSb[pair] = S;
    }

    __syncthreads();

    if (dir == 0) {
        // logZ = log( sum_c alpha_MID[c] * w_MID[c] ) + S_f + S_b
        float term = bflo(vpack) * warr[pair][2 * lane]
                   + bfhi(vpack) * warr[pair][2 * lane + 1];
#pragma unroll
        for (int o = 16; o; o >>= 1) term += __shfl_xor_sync(0xffffffffu, term, o);
        if (lane == 0) g_part[b] = __logf(term) + S + sSb[pair];
    }
}

// ---------------------------------------------------------------------------
// Gold path score per batch (cheap gathers) — exact fp32.
// ---------------------------------------------------------------------------
__global__ void __launch_bounds__(256) scores_kernel(const float* __restrict__ em,
                                                     const float* __restrict__ T,
                                                     const float* __restrict__ mask,
                                                     const int* __restrict__ tags) {
    const int b   = blockIdx.x;
    const int tid = threadIdx.x;
    const float* emb = em + (size_t)b * (LL * CC);
    const float* mkb = mask + (size_t)b * LL;
    const int*   tgb = tags + (size_t)b * LL;

    float acc = 0.f, msum = 0.f;
    for (int t = tid; t < LL; t += 256) {
        msum += mkb[t];
        if (t >= 1) {
            int tg = tgb[t];
            int tq = tgb[t - 1];
            acc += (emb[(size_t)t * CC + tg] + T[tq * CC + tg]) * mkb[t];
        }
    }

    __shared__ float sacc[8], smsum[8];
#pragma unroll
    for (int o = 16; o; o >>= 1) {
        acc  += __shfl_xor_sync(0xffffffffu, acc, o);
        msum += __shfl_xor_sync(0xffffffffu, msum, o);
    }
    int lane = tid & 31, w = tid >> 5;
    if (lane == 0) { sacc[w] = acc; smsum[w] = msum; }
    __syncthreads();
    if (tid == 0) {
        float A = 0.f, M = 0.f;
#pragma unroll
        for (int i = 0; i < 8; ++i) { A += sacc[i]; M += smsum[i]; }
        int t0 = tgb[0];
        float s = A + emb[t0] + T[START_S * CC + t0];
        int last = (int)M - 1;               // mask sum of 1.0s is exact in fp32
        s += T[tgb[last] * CC + STOP_S];
        g_scores[b] = s;
    }
}

// ---------------------------------------------------------------------------
// mean(partition - scores)
// ---------------------------------------------------------------------------
__global__ void __launch_bounds__(512) finalize_kernel(float* __restrict__ out) {
    int tid = threadIdx.x;
    float d = g_part[tid] - g_scores[tid];
    __shared__ float sh[16];
#pragma unroll
    for (int o = 16; o; o >>= 1) d += __shfl_xor_sync(0xffffffffu, d, o);
    if ((tid & 31) == 0) sh[tid >> 5] = d;
    __syncthreads();
    if (tid < 16) {
        float x = sh[tid];
#pragma unroll
        for (int o = 8; o; o >>= 1) x += __shfl_xor_sync(0x0000ffffu, x, o);
        if (tid == 0) out[0] = x * (1.0f / BB);
    }
}

extern "C" void kernel_launch(void* const* d_in, const int* in_sizes, int n_in,
                              void* d_out, int out_size) {
    (void)in_sizes; (void)n_in; (void)out_size;
    const float* em   = (const float*)d_in[0];
    const float* T    = (const float*)d_in[1];
    const float* mask = (const float*)d_in[2];
    const int*   tags = (const int*)d_in[3];
    float* out = (float*)d_out;

    prep_kernel<<<4, 512>>>(T);
    alpha_kernel<<<BB / 2, 128>>>(em, mask);
    scores_kernel<<<BB, 256>>>(em, T, mask, tags);
    finalize_kernel<<<1, 512>>>(out);
}

// round 16
// speedup vs baseline: 1.4428x; 1.0458x over previous
#include <cuda_runtime.h>
#include <cuda_bf16.h>

#define BB 512
#define LL 2048
#define CC 64
#define START_S 62
#define STOP_S 63
#define MID 1023

// scratch (no cudaMalloc allowed)
__device__ unsigned g_eTbfF[CC * 32]; // fwd:  [cp][k2] = bf16x2{exp(T[2k2][cp]), exp(T[2k2+1][cp])}
__device__ unsigned g_eTbfB[CC * 32]; // bwd:  [c][k2]  = bf16x2{exp(T[c][2k2]),  exp(T[c][2k2+1])}
__device__ float g_eTstop[CC];        // exp(T[c][STOP])
__device__ float g_trow_start[CC];    // T[START][c]
__device__ float g_part[BB];
__device__ float g_scores[BB];

// bf16x2 packed ops
__device__ __forceinline__ unsigned bffma(unsigned a, unsigned b, unsigned c) {
    unsigned d;
    asm("fma.rn.bf16x2 %0, %1, %2, %3;" : "=r"(d) : "r"(a), "r"(b), "r"(c));
    return d;
}
__device__ __forceinline__ unsigned bfadd(unsigned a, unsigned b) {
    unsigned d;
    asm("add.rn.bf16x2 %0, %1, %2;" : "=r"(d) : "r"(a), "r"(b));
    return d;
}
__device__ __forceinline__ float bfsum(unsigned ab) {
    float lo = __uint_as_float(ab << 16);
    float hi = __uint_as_float(ab & 0xffff0000u);
    return lo + hi;
}
__device__ __forceinline__ unsigned bfpack(float x, float y) {
    unsigned d;
    asm("cvt.rn.bf16x2.f32 %0, %1, %2;" : "=r"(d) : "f"(y), "f"(x));
    return d;
}

// ---------------------------------------------------------------------------
// Precompute both packed exp(T) tables + boundary vectors.
// ---------------------------------------------------------------------------
__global__ void prep_kernel(const float* __restrict__ T) {
    int i = blockIdx.x * blockDim.x + threadIdx.x;
    if (i < CC * 32) {
        int c  = i >> 5;
        int k2 = i & 31;
        __nv_bfloat162 pf = __floats2bfloat162_rn(__expf(T[(2 * k2) * CC + c]),
                                                  __expf(T[(2 * k2 + 1) * CC + c]));
        g_eTbfF[i] = *reinterpret_cast<unsigned*>(&pf);
        __nv_bfloat162 pb = __floats2bfloat162_rn(__expf(T[c * CC + 2 * k2]),
                                                  __expf(T[c * CC + 2 * k2 + 1]));
        g_eTbfB[i] = *reinterpret_cast<unsigned*>(&pb);
    }
    if (i < CC) {
        g_eTstop[i]     = __expf(T[i * CC + STOP_S]);
        g_trow_start[i] = T[START_S * CC + i];
    }
}

// two interleaved 64-dots in bf16x2 (this lane's two output states)
__device__ __forceinline__ void dot2(const unsigned* __restrict__ vsh32,
                                     const unsigned* __restrict__ eA,
                                     const unsigned* __restrict__ eB,
                                     float& ra, float& rb) {
    const uint4* q = reinterpret_cast<const uint4*>(vsh32);
    unsigned a0 = 0, a1 = 0, a2 = 0, a3 = 0;
    unsigned b0 = 0, b1 = 0, b2 = 0, b3 = 0;
#pragma unroll
    for (int j = 0; j < 8; ++j) {
        uint4 x = q[j];
        a0 = bffma(x.x, eA[4 * j + 0], a0);
        b0 = bffma(x.x, eB[4 * j + 0], b0);
        a1 = bffma(x.y, eA[4 * j + 1], a1);
        b1 = bffma(x.y, eB[4 * j + 1], b1);
        a2 = bffma(x.z, eA[4 * j + 2], a2);
        b2 = bffma(x.z, eB[4 * j + 2], b2);
        a3 = bffma(x.w, eA[4 * j + 3], a3);
        b3 = bffma(x.w, eB[4 * j + 3], b3);
    }
    ra = bfsum(bfadd(bfadd(a0, a1), bfadd(a2, a3)));
    rb = bfsum(bfadd(bfadd(b0, b1), bfadd(b2, b3)));
}

// forward step: v' = (e_t ⊙ (expT^T v)) ; MODE: 0 plain, 1 launch max, 2 renorm
template <int MODE>
__device__ __forceinline__ void stepF(float2 ev, float mkv,
                                      float& v0, float& v1, float& S, float& mx,
                                      int& cur, unsigned (*vsh)[32],
                                      const unsigned* __restrict__ eA,
                                      const unsigned* __restrict__ eB,
                                      int lane) {
    if (MODE == 1) {
        float x = fmaxf(v0, v1);
#pragma unroll
        for (int o = 16; o; o >>= 1) x = fmaxf(x, __shfl_xor_sync(0xffffffffu, x, o));
        mx = x;
    }
    float ee0 = __expf(ev.x);
    float ee1 = __expf(ev.y);
    float vr0 = v0, vr1 = v1;
    if (MODE == 2) {
        float r = __fdividef(1.0f, mx);
        S += __logf(mx);
        ee0 *= r; vr0 = v0 * r;
        ee1 *= r; vr1 = v1 * r;
    }
    float a, bq;
    dot2(vsh[cur], eA, eB, a, bq);
    float nv0 = (mkv > 0.f) ? a  * ee0 : vr0;
    float nv1 = (mkv > 0.f) ? bq * ee1 : vr1;
    v0 = nv0; v1 = nv1;
    vsh[cur ^ 1][lane] = bfpack(nv0, nv1);
    __syncwarp();
    cur ^= 1;
}

// backward step: w' = expT (e_{t+1} ⊙ w) ; emission applied BEFORE the dot
template <int MODE>
__device__ __forceinline__ void stepB(float2 ev, float mkv,
                                      float& v0, float& v1, float& S, float& mx,
                                      int& cur, unsigned (*vsh)[32],
                                      const unsigned* __restrict__ eA,
                                      const unsigned* __restrict__ eB,
                                      int lane) {
    if (MODE == 1) {
        float x = fmaxf(v0, v1);
#pragma unroll
        for (int o = 16; o; o >>= 1) x = fmaxf(x, __shfl_xor_sync(0xffffffffu, x, o));
        mx = x;
    }
    float ee0 = __expf(ev.x);
    float ee1 = __expf(ev.y);
    float vr0 = v0, vr1 = v1;
    if (MODE == 2) {
        float r = __fdividef(1.0f, mx);
        S += __logf(mx);
        ee0 *= r; vr0 = v0 * r;
        ee1 *= r; vr1 = v1 * r;
    }
    int nxt = cur ^ 1;
    vsh[nxt][lane] = bfpack(v0 * ee0, v1 * ee1);   // u = e⊙w (renorm folded in ee)
    __syncwarp();
    float a, bq;
    dot2(vsh[nxt], eA, eB, a, bq);
    v0 = (mkv > 0.f) ? a  : vr0;
    v1 = (mkv > 0.f) ? bq : vr1;
    cur = nxt;
}

// ---------------------------------------------------------------------------
// Bidirectional forward algorithm in exp-space, bf16 matvec, with the gold
// path score FUSED as a 5th warp — removes the separate scores_kernel launch
// (its latency-bound gathers hide completely under the 1024-step recursion).
// 256 CTAs x 160 threads = 2 batches/CTA:
//   warps 0-3: (fwd_b0, bwd_b0, fwd_b1, bwd_b1) on SMSPs 0-3 (R12 layout);
//   warp 4  : exact fp32 gold score for both batches.
// Renorm every 8 steps (growth <= ~e^50 worst typical window, safe in fp32;
// both directions renormalize once more in the epilogue so the final
// alpha·w product cannot overflow). Max-shuffles pipelined off the chain.
//   logZ = log( sum_c alpha_MID[c] * w_MID[c] ) + S_f + S_b.
// ---------------------------------------------------------------------------
__global__ void __launch_bounds__(160, 1) alpha_kernel(const float* __restrict__ em,
                                                       const float* __restrict__ Tm,
                                                       const float* __restrict__ mask,
                                                       const int* __restrict__ tags) {
    const int lane = threadIdx.x & 31;
    const int wid  = threadIdx.x >> 5;

    __shared__ __align__(16) unsigned vshbuf[4][2][32];  // [warp][buf][lane]
    __shared__ float warr[2][CC];
    __shared__ float sSb[2];

    if (wid == 4) {
        // ---------------- gold-score warp: both batches, exact fp32 ----------
#pragma unroll 1
        for (int pp = 0; pp < 2; ++pp) {
            const int bb = blockIdx.x * 2 + pp;
            const float* embS = em + (size_t)bb * (LL * CC);
            const float* mkbS = mask + (size_t)bb * LL;
            const int*   tgbS = tags + (size_t)bb * LL;
            float acc = 0.f, msum = 0.f;
#pragma unroll 1
            for (int t = lane; t < LL; t += 32) {
                float mval = mkbS[t];
                msum += mval;
                if (t >= 1) {
                    int tg = tgbS[t];
                    int tq = tgbS[t - 1];
                    acc += (embS[(size_t)t * CC + tg] + Tm[tq * CC + tg]) * mval;
                }
            }
#pragma unroll
            for (int o = 16; o; o >>= 1) {
                acc  += __shfl_xor_sync(0xffffffffu, acc, o);
                msum += __shfl_xor_sync(0xffffffffu, msum, o);
            }
            if (lane == 0) {
                int t0 = tgbS[0];
                float s = acc + embS[t0] + Tm[START_S * CC + t0];
                int last = (int)msum - 1;      // mask sum of 1.0s exact in fp32
                s += Tm[tgbS[last] * CC + STOP_S];
                g_scores[bb] = s;
            }
        }
        __syncthreads();
        return;
    }

    const int pair = wid >> 1;           // batch slot in CTA (0 or 1)
    const int dir  = wid & 1;            // 0 = forward, 1 = backward
    const int b    = blockIdx.x * 2 + pair;

    const float* emb = em + (size_t)b * (LL * CC);
    const float* mkb = mask + (size_t)b * LL;
    const float2* emb2 = reinterpret_cast<const float2*>(emb) + lane;

    unsigned (*vsh)[32] = vshbuf[wid];

    float v0, v1, S = 0.0f, mx = 0.0f;

    if (dir == 0) {
        // ---------------- forward half: steps 1..MID ----------------
        unsigned eA[32], eB[32];
        {
            const unsigned* ga = g_eTbfF + (2 * lane) * 32;
            const unsigned* gb = g_eTbfF + (2 * lane + 1) * 32;
#pragma unroll
            for (int k = 0; k < 32; ++k) { eA[k] = ga[k]; eB[k] = gb[k]; }
        }
        v0 = __expf(emb2[0].x + g_trow_start[2 * lane]);
        v1 = __expf(emb2[0].y + g_trow_start[2 * lane + 1]);
        vsh[0][lane] = bfpack(v0, v1);

        float2 ea = emb2[1 * 32], eb = emb2[2 * 32], ec = emb2[3 * 32];
        float  ma = mkb[1],       mb = mkb[2],       mc = mkb[3];
        __syncwarp();

        int cur = 0;
#define ADVF(t_)                                                        \
        {                                                               \
            int ti = (t_) + 3; if (ti > MID) ti = MID;                  \
            float2 en = emb2[(size_t)ti * 32];                          \
            float  mn = mkb[ti];                                        \
            ea = eb; ma = mb; eb = ec; mb = mc; ec = en; mc = mn;       \
        }
#define SF(MODE, t_)                                                    \
        {                                                               \
            float2 e0 = ea; float m0 = ma; ADVF(t_);                    \
            stepF<MODE>(e0, m0, v0, v1, S, mx, cur, vsh, eA, eB, lane); \
        }
        // 127 octets: steps 1..1016, renorm measured at 8k+1 / applied 8k+2
#pragma unroll 1
        for (int t = 1; t + 7 <= 1016; t += 8) {
            SF(1, t); SF(2, t + 1); SF(0, t + 2); SF(0, t + 3);
            SF(0, t + 4); SF(0, t + 5); SF(0, t + 6); SF(0, t + 7);
        }
        // tail: steps 1017..1023 with one more renorm to bound the window
        SF(1, 1017); SF(2, 1018);
#pragma unroll 1
        for (int t = 1019; t <= MID; ++t) { SF(0, t); }
#undef SF
#undef ADVF
        // epilogue renorm so the final alpha·w product cannot overflow
        {
            float x = fmaxf(v0, v1);
#pragma unroll
            for (int o = 16; o; o >>= 1) x = fmaxf(x, __shfl_xor_sync(0xffffffffu, x, o));
            float r = __fdividef(1.0f, x);
            v0 *= r; v1 *= r; S += __logf(x);
        }
    } else {
        // ---------------- backward half: steps L-2 .. MID ----------------
        unsigned eA[32], eB[32];
        {
            const unsigned* ga = g_eTbfB + (2 * lane) * 32;
            const unsigned* gb = g_eTbfB + (2 * lane + 1) * 32;
#pragma unroll
            for (int k = 0; k < 32; ++k) { eA[k] = ga[k]; eB[k] = gb[k]; }
        }
        v0 = g_eTstop[2 * lane];
        v1 = g_eTstop[2 * lane + 1];

        float2 ea = emb2[(size_t)(LL - 1) * 32];
        float2 eb = emb2[(size_t)(LL - 2) * 32];
        float2 ec = emb2[(size_t)(LL - 3) * 32];
        float  ma = mkb[LL - 1], mb = mkb[LL - 2], mc = mkb[LL - 3];
        __syncwarp();

        int cur = 0;
#define ADVB(t_)                                                        \
        {                                                               \
            int ti = (t_) - 2; if (ti < 0) ti = 0;                      \
            float2 en = emb2[(size_t)ti * 32];                          \
            float  mn = mkb[ti];                                        \
            ea = eb; ma = mb; eb = ec; mb = mc; ec = en; mc = mn;       \
        }
#define SB(MODE, t_)                                                    \
        {                                                               \
            float2 e0 = ea; float m0 = ma; ADVB(t_);                    \
            stepB<MODE>(e0, m0, v0, v1, S, mx, cur, vsh, eA, eB, lane); \
        }
        // 128 octets = 1024 steps: emissions LL-1 down to MID+1
#pragma unroll 1
        for (int t = LL - 2; t > MID; t -= 8) {
            SB(1, t); SB(2, t - 1); SB(0, t - 2); SB(0, t - 3);
            SB(0, t - 4); SB(0, t - 5); SB(0, t - 6); SB(0, t - 7);
        }
#undef SB
#undef ADVB
        // epilogue renorm (overflow guard for the combine)
        {
            float x = fmaxf(v0, v1);
#pragma unroll
            for (int o = 16; o; o >>= 1) x = fmaxf(x, __shfl_xor_sync(0xffffffffu, x, o));
            float r = __fdividef(1.0f, x);
            v0 *= r; v1 *= r; S += __logf(x);
        }
        warr[pair][2 * lane]     = v0;
        warr[pair][2 * lane + 1] = v1;
        if (lane == 0) sSb[pair] = S;
    }

    __syncthreads();

    if (dir == 0) {
        // logZ = log( sum_c alpha_MID[c] * w_MID[c] ) + S_f + S_b
        float term = v0 * warr[pair][2 * lane] + v1 * warr[pair][2 * lane + 1];
#pragma unroll
        for (int o = 16; o; o >>= 1) term += __shfl_xor_sync(0xffffffffu, term, o);
        if (lane == 0) g_part[b] = __logf(term) + S + sSb[pair];
    }
}

// ---------------------------------------------------------------------------
// mean(partition - scores)
// ---------------------------------------------------------------------------
__global__ void __launch_bounds__(512) finalize_kernel(float* __restrict__ out) {
    int tid = threadIdx.x;
    float d = g_part[tid] - g_scores[tid];
    __shared__ float sh[16];
#pragma unroll
    for (int o = 16; o; o >>= 1) d += __shfl_xor_sync(0xffffffffu, d, o);
    if ((tid & 31) == 0) sh[tid >> 5] = d;
    __syncthreads();
    if (tid < 16) {
        float x = sh[tid];
#pragma unroll
        for (int o = 8; o; o >>= 1) x += __shfl_xor_sync(0x0000ffffu, x, o);
        if (tid == 0) out[0] = x * (1.0f / BB);
    }
}

extern "C" void kernel_launch(void* const* d_in, const int* in_sizes, int n_in,
                              void* d_out, int out_size) {
    (void)in_sizes; (void)n_in; (void)out_size;
    const float* em   = (const float*)d_in[0];
    const float* T    = (const float*)d_in[1];
    const float* mask = (const float*)d_in[2];
    const int*   tags = (const int*)d_in[3];
    float* out = (float*)d_out;

    prep_kernel<<<4, 512>>>(T);
    alpha_kernel<<<BB / 2, 160>>>(em, T, mask, tags);
    finalize_kernel<<<1, 512>>>(out);
}